// round 4
// baseline (speedup 1.0000x reference)
#include <cuda_runtime.h>
#include <cstdint>

typedef unsigned long long u64;

#define Bsz    256
#define Ssz    512
#define Tsz    20
#define Esz    25
#define Hsz    128
#define SKIPsz 64
#define Gsz    512            // 4*H
#define NROWS  (Bsz*Ssz)      // 131072 ; row r = t*256 + b (t-major)

// ---------------- scratch (static device globals; no allocation) ----------
__device__ float g_xpool[(size_t)NROWS * Esz];        // [t*256+b][25]
__device__ float g_mask [(size_t)NROWS];              // [t*256+b]
__device__ float g_P    [(size_t)2 * NROWS * Gsz];    // [dir][t*256+b][512]
__device__ float g_out  [(size_t)NROWS * 256];        // [b*512+t][256] (f|b)
__device__ float g_hf   [(size_t)Bsz * Hsz];          // final fwd h
__device__ float g_qwq  [(size_t)Bsz * Hsz];          // h_fwd@Wq + bq
__device__ float g_energy[(size_t)NROWS];             // [b*512+t]

// ---------------- f32x2 helpers -------------------------------------------
__device__ __forceinline__ u64 pk(float a, float b) {
    u64 r;
    asm("mov.b64 %0, {%1, %2};" : "=l"(r) : "r"(__float_as_uint(a)), "r"(__float_as_uint(b)));
    return r;
}
__device__ __forceinline__ void upk(u64 v, float& a, float& b) {
    unsigned lo, hi;
    asm("mov.b64 {%0, %1}, %2;" : "=r"(lo), "=r"(hi) : "l"(v));
    a = __uint_as_float(lo); b = __uint_as_float(hi);
}
__device__ __forceinline__ void fma2(u64& d, u64 a, u64 b) {
    asm("fma.rn.f32x2 %0, %1, %2, %0;" : "+l"(d) : "l"(a), "l"(b));
}

// ---------------- math helpers --------------------------------------------
__device__ __forceinline__ float sigf(float x) {
    return __fdividef(1.f, 1.f + __expf(-x));
}
__device__ __forceinline__ float tanhpr(float x) {
    return __fdividef(2.f, 1.f + __expf(-2.f * x)) - 1.f;
}

// ================= K1: embedding mean-pool + step mask =====================
__global__ void k_embed(const int* __restrict__ tags, const float* __restrict__ emb) {
    int g    = blockIdx.x * 8 + (threadIdx.x >> 5);
    int lane = threadIdx.x & 31;
    if (g >= NROWS) return;
    int b = g >> 9, s = g & 511;
    const int* tg = tags + (size_t)g * Tsz;
    float acc = 0.f; int cnt = 0; int first = 0;
    #pragma unroll
    for (int i = 0; i < Tsz; i++) {
        int tv = __ldg(tg + i);
        if (i == 0) first = tv;
        if (tv != 0) {
            cnt++;
            if (lane < Esz) acc += __ldg(emb + (size_t)tv * Esz + lane);
        }
    }
    int r = s * Bsz + b;
    if (lane < Esz) g_xpool[(size_t)r * Esz + lane] = acc / (cnt ? (float)cnt : 1.f);
    if (lane == 0)  g_mask[r] = (first != 0) ? 1.f : 0.f;
}

// ================= K2: prologue GEMM  P = x@K + skip@Sk + bias =============
__global__ __launch_bounds__(512, 1)
void k_prologue(const float* __restrict__ skips,
                const float* __restrict__ Kw, const float* __restrict__ Sw,
                const float* __restrict__ bw, int d) {
    __shared__ __align__(16) u64 xs2[8][48];
    int j = threadIdx.x;

    u64 wr[48];
    #pragma unroll
    for (int p = 0; p < 48; p++) {
        float a = 0.f, b2 = 0.f;
        int k0 = 2 * p, k1 = 2 * p + 1;
        if (k0 < Esz)      a  = __ldg(Kw + k0 * Gsz + j);
        else if (k0 < 89)  a  = __ldg(Sw + (k0 - Esz) * Gsz + j);
        if (k1 < Esz)      b2 = __ldg(Kw + k1 * Gsz + j);
        else if (k1 < 89)  b2 = __ldg(Sw + (k1 - Esz) * Gsz + j);
        wr[p] = pk(a, b2);
    }
    float bias = __ldg(bw + j);
    float* Pd = g_P + (size_t)d * NROWS * Gsz;

    int r0 = blockIdx.x * 1792;
    for (int rt = 0; rt < 1792; rt += 8) {
        int rb = r0 + rt;
        if (rb >= NROWS) break;
        __syncthreads();
        if (j < 384) {
            int rr = j / 48, p = j % 48;
            int r = rb + rr;
            float a = 0.f, b2 = 0.f;
            if (r < NROWS) {
                int bb2 = r & 255, tt = r >> 8;
                int k0 = 2 * p, k1 = 2 * p + 1;
                if (k0 < Esz)     a  = g_xpool[(size_t)r * Esz + k0];
                else if (k0 < 89) a  = __ldg(skips + ((size_t)(bb2 << 9) + tt) * SKIPsz + (k0 - Esz));
                if (k1 < Esz)     b2 = g_xpool[(size_t)r * Esz + k1];
                else if (k1 < 89) b2 = __ldg(skips + ((size_t)(bb2 << 9) + tt) * SKIPsz + (k1 - Esz));
            }
            xs2[rr][p] = pk(a, b2);
        }
        __syncthreads();
        #pragma unroll 1
        for (int rr = 0; rr < 8; rr++) {
            int r = rb + rr;
            if (r >= NROWS) break;
            u64 z0 = pk(bias, 0.f), z1 = pk(0.f, 0.f);
            #pragma unroll
            for (int q = 0; q < 24; q++) {
                ulonglong2 xv = *(const ulonglong2*)&xs2[rr][2 * q];
                fma2(z0, xv.x, wr[2 * q]);
                fma2(z1, xv.y, wr[2 * q + 1]);
            }
            float l0, h0, l1, h1; upk(z0, l0, h0); upk(z1, l1, h1);
            Pd[(size_t)r * Gsz + j] = (l0 + h0) + (l1 + h1);
        }
    }
}

// ================= K3: LSTM recurrence ======================================
// grid (64, 2): block = (4 batches, dir), 1 wave. 256 threads; thread u owns
// gate columns u and u+256 for all 4 batches.
// R pairs 0..35 (rows 0..71) in regs per col; pairs 36..63 in smem.
#define LSTM_SMEM (114688 + 2048 + 8192 + 8192)
__global__ __launch_bounds__(256, 1)
void k_lstm(const float* __restrict__ Rf, const float* __restrict__ Rb) {
    extern __shared__ __align__(16) char smraw[];
    ulonglong2* R4  = (ulonglong2*)smraw;                    // [w*512+col], w=0..13 -> pairs 36+2w,37+2w
    u64*   h2s = (u64*)(smraw + 114688);                     // [p*4+nb], p=0..63
    float* z_sm = (float*)(smraw + 114688 + 2048);           // [nb*512+col]
    float* msk  = (float*)(smraw + 114688 + 2048 + 8192);    // [t*4+nb]

    int u = threadIdx.x, d = blockIdx.y, bg = blockIdx.x;
    int colA = u, colB = u + 256;
    const float* R = d ? Rb : Rf;

    u64 RA[36], RB[36];
    #pragma unroll
    for (int p = 0; p < 36; p++) {
        RA[p] = pk(__ldg(R + (2 * p) * Gsz + colA), __ldg(R + (2 * p + 1) * Gsz + colA));
        RB[p] = pk(__ldg(R + (2 * p) * Gsz + colB), __ldg(R + (2 * p + 1) * Gsz + colB));
    }
    #pragma unroll 1
    for (int e = u; e < 14 * 512; e += 256) {
        int w = e >> 9, col = e & 511;
        int r0 = 72 + 4 * w;
        ulonglong2 v;
        v.x = pk(__ldg(R + (r0 + 0) * Gsz + col), __ldg(R + (r0 + 1) * Gsz + col));
        v.y = pk(__ldg(R + (r0 + 2) * Gsz + col), __ldg(R + (r0 + 3) * Gsz + col));
        R4[e] = v;
    }
    h2s[u] = 0ULL;
    for (int e = u; e < 2048; e += 256)
        msk[e] = g_mask[(e >> 2) * Bsz + 4 * bg + (e & 3)];

    int nb = u >> 6, q = u & 63;
    int bq2 = 4 * bg + nb;
    float c0 = 0.f, c1 = 0.f, hp0 = 0.f, hp1 = 0.f;

    const float* Pd = g_P + (size_t)d * NROWS * Gsz;
    int t = d ? (Ssz - 1) : 0;
    int dt = d ? -1 : 1;
    float pvA0 = Pd[((size_t)(t * Bsz + 4 * bg + 0)) * Gsz + colA];
    float pvA1 = Pd[((size_t)(t * Bsz + 4 * bg + 1)) * Gsz + colA];
    float pvA2 = Pd[((size_t)(t * Bsz + 4 * bg + 2)) * Gsz + colA];
    float pvA3 = Pd[((size_t)(t * Bsz + 4 * bg + 3)) * Gsz + colA];
    float pvB0 = Pd[((size_t)(t * Bsz + 4 * bg + 0)) * Gsz + colB];
    float pvB1 = Pd[((size_t)(t * Bsz + 4 * bg + 1)) * Gsz + colB];
    float pvB2 = Pd[((size_t)(t * Bsz + 4 * bg + 2)) * Gsz + colB];
    float pvB3 = Pd[((size_t)(t * Bsz + 4 * bg + 3)) * Gsz + colB];
    __syncthreads();

    #pragma unroll 1
    for (int i = 0; i < Ssz; i++) {
        u64 aA0 = pk(pvA0, 0.f), aA1 = pk(pvA1, 0.f), aA2 = pk(pvA2, 0.f), aA3 = pk(pvA3, 0.f);
        u64 aB0 = pk(pvB0, 0.f), aB1 = pk(pvB1, 0.f), aB2 = pk(pvB2, 0.f), aB3 = pk(pvB3, 0.f);
        #pragma unroll
        for (int p = 0; p < 36; p++) {
            ulonglong2 ha = *(const ulonglong2*)&h2s[4 * p];
            ulonglong2 hb = *(const ulonglong2*)&h2s[4 * p + 2];
            fma2(aA0, ha.x, RA[p]); fma2(aA1, ha.y, RA[p]);
            fma2(aA2, hb.x, RA[p]); fma2(aA3, hb.y, RA[p]);
            fma2(aB0, ha.x, RB[p]); fma2(aB1, ha.y, RB[p]);
            fma2(aB2, hb.x, RB[p]); fma2(aB3, hb.y, RB[p]);
        }
        #pragma unroll
        for (int w = 0; w < 14; w++) {
            ulonglong2 rA = R4[w * 512 + colA];
            ulonglong2 rB = R4[w * 512 + colB];
            int p0 = 36 + 2 * w;
            ulonglong2 ha0 = *(const ulonglong2*)&h2s[4 * p0];
            ulonglong2 hb0 = *(const ulonglong2*)&h2s[4 * p0 + 2];
            ulonglong2 ha1 = *(const ulonglong2*)&h2s[4 * p0 + 4];
            ulonglong2 hb1 = *(const ulonglong2*)&h2s[4 * p0 + 6];
            fma2(aA0, ha0.x, rA.x); fma2(aA1, ha0.y, rA.x);
            fma2(aA2, hb0.x, rA.x); fma2(aA3, hb0.y, rA.x);
            fma2(aA0, ha1.x, rA.y); fma2(aA1, ha1.y, rA.y);
            fma2(aA2, hb1.x, rA.y); fma2(aA3, hb1.y, rA.y);
            fma2(aB0, ha0.x, rB.x); fma2(aB1, ha0.y, rB.x);
            fma2(aB2, hb0.x, rB.x); fma2(aB3, hb0.y, rB.x);
            fma2(aB0, ha1.x, rB.y); fma2(aB1, ha1.y, rB.y);
            fma2(aB2, hb1.x, rB.y); fma2(aB3, hb1.y, rB.y);
        }
        {
            float lo, hi;
            upk(aA0, lo, hi); z_sm[0 * 512 + colA] = lo + hi;
            upk(aA1, lo, hi); z_sm[1 * 512 + colA] = lo + hi;
            upk(aA2, lo, hi); z_sm[2 * 512 + colA] = lo + hi;
            upk(aA3, lo, hi); z_sm[3 * 512 + colA] = lo + hi;
            upk(aB0, lo, hi); z_sm[0 * 512 + colB] = lo + hi;
            upk(aB1, lo, hi); z_sm[1 * 512 + colB] = lo + hi;
            upk(aB2, lo, hi); z_sm[2 * 512 + colB] = lo + hi;
            upk(aB3, lo, hi); z_sm[3 * 512 + colB] = lo + hi;
        }
        int tn = t + dt;
        float pnA0 = 0.f, pnA1 = 0.f, pnA2 = 0.f, pnA3 = 0.f;
        float pnB0 = 0.f, pnB1 = 0.f, pnB2 = 0.f, pnB3 = 0.f;
        if (i < Ssz - 1) {
            pnA0 = Pd[((size_t)(tn * Bsz + 4 * bg + 0)) * Gsz + colA];
            pnA1 = Pd[((size_t)(tn * Bsz + 4 * bg + 1)) * Gsz + colA];
            pnA2 = Pd[((size_t)(tn * Bsz + 4 * bg + 2)) * Gsz + colA];
            pnA3 = Pd[((size_t)(tn * Bsz + 4 * bg + 3)) * Gsz + colA];
            pnB0 = Pd[((size_t)(tn * Bsz + 4 * bg + 0)) * Gsz + colB];
            pnB1 = Pd[((size_t)(tn * Bsz + 4 * bg + 1)) * Gsz + colB];
            pnB2 = Pd[((size_t)(tn * Bsz + 4 * bg + 2)) * Gsz + colB];
            pnB3 = Pd[((size_t)(tn * Bsz + 4 * bg + 3)) * Gsz + colB];
        }
        __syncthreads();
        {
            float m = msk[t * 4 + nb];
            const float* zz = z_sm + nb * 512 + 2 * q;
            float2 zi = *(const float2*)(zz);
            float2 zf = *(const float2*)(zz + 128);
            float2 zg = *(const float2*)(zz + 256);
            float2 zo = *(const float2*)(zz + 384);
            float cn0 = sigf(zf.x) * c0 + sigf(zi.x) * tanhpr(zg.x);
            float hn0 = sigf(zo.x) * tanhpr(cn0);
            float cn1 = sigf(zf.y) * c1 + sigf(zi.y) * tanhpr(zg.y);
            float hn1 = sigf(zo.y) * tanhpr(cn1);
            bool mm = (m != 0.f);
            float h0 = mm ? hn0 : hp0; c0 = mm ? cn0 : c0;
            float h1 = mm ? hn1 : hp1; c1 = mm ? cn1 : c1;
            hp0 = h0; hp1 = h1;
            h2s[q * 4 + nb] = pk(h0, h1);
            *(float2*)(g_out + ((((size_t)bq2 << 9) + t)) * 256 + (d << 7) + 2 * q) = make_float2(h0, h1);
            if (d == 0 && i == Ssz - 1) {
                g_hf[bq2 * Hsz + 2 * q]     = h0;
                g_hf[bq2 * Hsz + 2 * q + 1] = h1;
            }
        }
        __syncthreads();
        pvA0 = pnA0; pvA1 = pnA1; pvA2 = pnA2; pvA3 = pnA3;
        pvB0 = pnB0; pvB1 = pnB1; pvB2 = pnB2; pvB3 = pnB3;
        t = tn;
    }
}

// ================= K4: queries = h_fwd @ Wq + bq ============================
__global__ void k_qw(const float* __restrict__ Wq, const float* __restrict__ bq) {
    __shared__ float hf[Hsz];
    int b = blockIdx.x, i = threadIdx.x;
    hf[i] = g_hf[b * Hsz + i];
    __syncthreads();
    float acc = __ldg(bq + i);
    #pragma unroll 8
    for (int k = 0; k < Hsz; k++) acc = fmaf(hf[k], __ldg(Wq + k * Hsz + i), acc);
    g_qwq[b * Hsz + i] = acc;
}

// ================= K5: keys GEMM + tanh + energy ============================
__global__ __launch_bounds__(512, 1)
void k_keys(const float* __restrict__ Wk, const float* __restrict__ bk,
            const float* __restrict__ We, const float* __restrict__ be) {
    __shared__ __align__(16) u64 row2[4][128];
    __shared__ float qb[128], bks[128];
    __shared__ float partial[3][4][128];
    __shared__ float part2[4][4];

    int tid = threadIdx.x;
    int jc = tid & 127, qtr = tid >> 7;
    int blk = blockIdx.x;
    int b = blk >> 2;
    int r0 = blk * 128;

    u64 wq[32];
    #pragma unroll
    for (int i = 0; i < 32; i++) {
        int k0 = qtr * 64 + 2 * i;
        wq[i] = pk(__ldg(Wk + (size_t)k0 * Hsz + jc), __ldg(Wk + (size_t)(k0 + 1) * Hsz + jc));
    }
    if (tid < 128) { qb[tid] = g_qwq[b * Hsz + tid]; bks[tid] = __ldg(bk + tid); }
    float Wej = __ldg(We + jc);
    float bev = __ldg(be);
    __syncthreads();

    #pragma unroll 1
    for (int rr = 0; rr < 128; rr += 4) {
        {
            int ro = tid >> 7, p = tid & 127;
            const float2 v = *(const float2*)(g_out + (size_t)(r0 + rr + ro) * 256 + 2 * p);
            row2[ro][p] = pk(v.x, v.y);
        }
        __syncthreads();

        u64 a0 = pk(0.f, 0.f), a1 = a0, a2 = a0, a3 = a0;
        #pragma unroll
        for (int it = 0; it < 16; it++) {
            int p = qtr * 32 + 2 * it;
            u64 w0 = wq[2 * it], w1 = wq[2 * it + 1];
            ulonglong2 r_0 = *(const ulonglong2*)&row2[0][p];
            ulonglong2 r_1 = *(const ulonglong2*)&row2[1][p];
            ulonglong2 r_2 = *(const ulonglong2*)&row2[2][p];
            ulonglong2 r_3 = *(const ulonglong2*)&row2[3][p];
            fma2(a0, r_0.x, w0); fma2(a0, r_0.y, w1);
            fma2(a1, r_1.x, w0); fma2(a1, r_1.y, w1);
            fma2(a2, r_2.x, w0); fma2(a2, r_2.y, w1);
            fma2(a3, r_3.x, w0); fma2(a3, r_3.y, w1);
        }
        float acc[4];
        { float lo, hi;
          upk(a0, lo, hi); acc[0] = lo + hi;
          upk(a1, lo, hi); acc[1] = lo + hi;
          upk(a2, lo, hi); acc[2] = lo + hi;
          upk(a3, lo, hi); acc[3] = lo + hi; }
        if (qtr > 0) {
            #pragma unroll
            for (int ro = 0; ro < 4; ro++) partial[qtr - 1][ro][jc] = acc[ro];
        }
        __syncthreads();
        if (qtr == 0) {
            #pragma unroll
            for (int ro = 0; ro < 4; ro++) {
                float z = acc[ro] + partial[0][ro][jc] + partial[1][ro][jc] + partial[2][ro][jc]
                        + bks[jc] + qb[jc];
                float v = Wej * tanhpr(z);
                #pragma unroll
                for (int o = 16; o > 0; o >>= 1) v += __shfl_down_sync(0xffffffffu, v, o);
                if ((jc & 31) == 0) part2[ro][jc >> 5] = v;
            }
        }
        __syncthreads();
        if (tid < 4) {
            float e = part2[tid][0] + part2[tid][1] + part2[tid][2] + part2[tid][3] + bev;
            int r2 = r0 + rr + tid;
            int tt = r2 & 511;
            float m = g_mask[tt * Bsz + b];
            g_energy[r2] = e - (1.f - m) * 1e9f;
        }
        __syncthreads();
    }
}

// ================= K6: softmax over t + context =============================
__global__ __launch_bounds__(256, 1)
void k_softctx(float* __restrict__ out) {
    __shared__ float wsm[512];
    __shared__ float red[256];
    int b = blockIdx.x, tid = threadIdx.x;
    float e0 = g_energy[(size_t)b * 512 + tid];
    float e1 = g_energy[(size_t)b * 512 + 256 + tid];
    red[tid] = fmaxf(e0, e1);
    __syncthreads();
    #pragma unroll
    for (int o = 128; o > 0; o >>= 1) {
        if (tid < o) red[tid] = fmaxf(red[tid], red[tid + o]);
        __syncthreads();
    }
    float mx = red[0];
    __syncthreads();
    float x0 = __expf(e0 - mx), x1 = __expf(e1 - mx);
    wsm[tid] = x0; wsm[256 + tid] = x1;
    red[tid] = x0 + x1;
    __syncthreads();
    #pragma unroll
    for (int o = 128; o > 0; o >>= 1) {
        if (tid < o) red[tid] += red[tid + o];
        __syncthreads();
    }
    float inv = __fdividef(1.f, red[0]);

    const float* ob = g_out + (size_t)b * 512 * 256;
    float acc = 0.f;
    #pragma unroll 4
    for (int t = 0; t < 512; t++)
        acc = fmaf(wsm[t], __ldg(ob + (size_t)t * 256 + tid), acc);
    out[(size_t)b * 256 + tid] = acc * inv;
}

// ================= launch ===================================================
extern "C" void kernel_launch(void* const* d_in, const int* in_sizes, int n_in,
                              void* d_out, int out_size) {
    const int*   tags  = (const int*)  d_in[0];
    const float* skips = (const float*)d_in[1];
    const float* emb   = (const float*)d_in[2];
    const float* Kf    = (const float*)d_in[3];
    const float* Rf    = (const float*)d_in[4];
    const float* Skf   = (const float*)d_in[5];
    const float* bf    = (const float*)d_in[6];
    const float* Kb    = (const float*)d_in[7];
    const float* Rb    = (const float*)d_in[8];
    const float* Skb   = (const float*)d_in[9];
    const float* bb    = (const float*)d_in[10];
    const float* Wk    = (const float*)d_in[11];
    const float* bk    = (const float*)d_in[12];
    const float* Wq    = (const float*)d_in[13];
    const float* bq    = (const float*)d_in[14];
    const float* We    = (const float*)d_in[15];
    const float* be    = (const float*)d_in[16];
    float* out = (float*)d_out;

    cudaFuncSetAttribute(k_lstm, cudaFuncAttributeMaxDynamicSharedMemorySize, LSTM_SMEM);

    k_embed<<<NROWS / 8, 256>>>(tags, emb);
    k_prologue<<<74, 512>>>(skips, Kf, Skf, bf, 0);
    k_prologue<<<74, 512>>>(skips, Kb, Skb, bb, 1);
    k_lstm<<<dim3(64, 2), 256, LSTM_SMEM>>>(Rf, Rb);
    k_qw<<<Bsz, Hsz>>>(Wq, bq);
    k_keys<<<1024, 512>>>(Wk, bk, We, be);
    k_softctx<<<Bsz, 256>>>(out);
}